// round 11
// baseline (speedup 1.0000x reference)
#include <cuda_runtime.h>
#include <cuda_bf16.h>
#include <cstdint>
#include <cstdio>

// ---------------- problem constants ----------------
#define Bq   256
#define Eq   512
#define Pq   512
#define Dq   768
#define Hq   8
#define DHq  96
#define CLq  40
#define PLq  40
#define Lq   8
#define MHq  1536
#define Nseq 80                 // CL + PL
#define ROWS (Bq * Nseq)        // 20480 token rows

// ---------------- scratch (device globals, no allocation) ----------------
__device__ float g_lat[Bq * Pq];                    // 256x512
__device__ float g_x  [(size_t)ROWS * Dq];          // residual stream
__device__ float g_h  [(size_t)ROWS * Dq];          // LN output
__device__ float g_q  [(size_t)ROWS * Dq];
__device__ float g_kv [(size_t)ROWS * 2 * Dq];
__device__ float g_o  [(size_t)ROWS * Dq];
__device__ float g_mid[(size_t)ROWS * MHq];

// =====================================================================
// TF32 tensor-core GEMM: C[M,N] = A[M,K] @ B[K,N] (+bias, +res, +relu)
// row-major. Requires M%128==0, N%128==0, K%16==0 (all shapes comply).
// Block tile 128x128x16, 256 threads = 8 warps (2x4), warp tile 64x32,
// per warp 4x4 mma.sync.m16n8k8.tf32 per 8-wide k-step.
// Double-buffered smem. A in smem as [m][20] (pad), B as [k][136] (pad):
// both give conflict-free fragment LDS.
// =====================================================================
#define ASTRIDE 20
#define BSTRIDE 136

__device__ __forceinline__ float f2tf32(float x) {
    uint32_t u;
    asm("cvt.rna.tf32.f32 %0, %1;" : "=r"(u) : "f"(x));
    return __uint_as_float(u);
}

__device__ __forceinline__ void mma_tf32(float4& d, const uint32_t a[4], const uint32_t b[2]) {
    asm volatile(
        "mma.sync.aligned.m16n8k8.row.col.f32.tf32.tf32.f32 "
        "{%0,%1,%2,%3}, {%4,%5,%6,%7}, {%8,%9}, {%0,%1,%2,%3};"
        : "+f"(d.x), "+f"(d.y), "+f"(d.z), "+f"(d.w)
        : "r"(a[0]), "r"(a[1]), "r"(a[2]), "r"(a[3]),
          "r"(b[0]), "r"(b[1]));
}

template <bool BIAS, bool RES, bool RELU>
__global__ __launch_bounds__(256)
void tf32gemm_k(const float* __restrict__ A, const float* __restrict__ B,
                float* __restrict__ C, const float* __restrict__ bias,
                const float* __restrict__ res,
                int M, int N, int K, int ldc)
{
    __shared__ float As[2][128 * ASTRIDE];   // [m][k] (k in 0..15, pad to 20)
    __shared__ float Bs[2][16 * BSTRIDE];    // [k][n] (n in 0..127, pad to 136)

    const int tid  = threadIdx.x;
    const int lane = tid & 31;
    const int warp = tid >> 5;
    const int warpM = warp >> 2;       // 0..1
    const int warpN = warp & 3;        // 0..3
    const int bm = blockIdx.y * 128;
    const int bn = blockIdx.x * 128;

    // global load mapping
    // A tile: 128 rows x 16 cols = 512 float4 chunks; thread t -> chunk t and t+256
    const int rowA = tid >> 2;                 // 0..63  (second chunk = +64)
    const int kqA  = (tid & 3) * 4;            // 0,4,8,12
    // B tile: 16 rows x 128 cols = 512 float4 chunks
    const int kB   = tid >> 5;                 // 0..7   (second chunk = +8)
    const int nB   = (tid & 31) * 4;           // 0..124

    const float* aG = A + (size_t)(bm + rowA) * K + kqA;
    const float* bG = B + (size_t)kB * N + bn + nB;
    const size_t aG2 = (size_t)64 * K;         // offset to second A chunk
    const size_t bG2 = (size_t)8 * N;          // offset to second B chunk

    float4 acc[4][4];
#pragma unroll
    for (int i = 0; i < 4; i++)
#pragma unroll
        for (int j = 0; j < 4; j++) acc[i][j] = make_float4(0.f, 0.f, 0.f, 0.f);

    // ---- preload tile 0 ----
    float4 pa0 = *reinterpret_cast<const float4*>(aG);
    float4 pa1 = *reinterpret_cast<const float4*>(aG + aG2);
    float4 pb0 = *reinterpret_cast<const float4*>(bG);
    float4 pb1 = *reinterpret_cast<const float4*>(bG + bG2);

    int s = 0;
    {
        float4 ca;
        ca.x = f2tf32(pa0.x); ca.y = f2tf32(pa0.y); ca.z = f2tf32(pa0.z); ca.w = f2tf32(pa0.w);
        *reinterpret_cast<float4*>(&As[0][rowA * ASTRIDE + kqA]) = ca;
        ca.x = f2tf32(pa1.x); ca.y = f2tf32(pa1.y); ca.z = f2tf32(pa1.z); ca.w = f2tf32(pa1.w);
        *reinterpret_cast<float4*>(&As[0][(rowA + 64) * ASTRIDE + kqA]) = ca;
        ca.x = f2tf32(pb0.x); ca.y = f2tf32(pb0.y); ca.z = f2tf32(pb0.z); ca.w = f2tf32(pb0.w);
        *reinterpret_cast<float4*>(&Bs[0][kB * BSTRIDE + nB]) = ca;
        ca.x = f2tf32(pb1.x); ca.y = f2tf32(pb1.y); ca.z = f2tf32(pb1.z); ca.w = f2tf32(pb1.w);
        *reinterpret_cast<float4*>(&Bs[0][(kB + 8) * BSTRIDE + nB]) = ca;
    }
    __syncthreads();

    const int T = K / 16;
    for (int t = 0; t < T; t++) {
        // prefetch next tile into registers
        if (t + 1 < T) {
            const int k0 = (t + 1) * 16;
            pa0 = *reinterpret_cast<const float4*>(aG + k0);
            pa1 = *reinterpret_cast<const float4*>(aG + k0 + aG2);
            pb0 = *reinterpret_cast<const float4*>(bG + (size_t)k0 * N);
            pb1 = *reinterpret_cast<const float4*>(bG + (size_t)k0 * N + bG2);
        }

        // compute two 8-wide k-steps from stage s
#pragma unroll
        for (int kk = 0; kk < 16; kk += 8) {
            const int kb = kk + (lane & 3);
            uint32_t afr[4][4];
            uint32_t bfr[4][2];
#pragma unroll
            for (int mt = 0; mt < 4; mt++) {
                const int m0 = warpM * 64 + mt * 16 + (lane >> 2);
                afr[mt][0] = __float_as_uint(As[s][m0 * ASTRIDE + kb]);
                afr[mt][1] = __float_as_uint(As[s][(m0 + 8) * ASTRIDE + kb]);
                afr[mt][2] = __float_as_uint(As[s][m0 * ASTRIDE + kb + 4]);
                afr[mt][3] = __float_as_uint(As[s][(m0 + 8) * ASTRIDE + kb + 4]);
            }
#pragma unroll
            for (int nt = 0; nt < 4; nt++) {
                const int n0 = warpN * 32 + nt * 8 + (lane >> 2);
                bfr[nt][0] = __float_as_uint(Bs[s][kb * BSTRIDE + n0]);
                bfr[nt][1] = __float_as_uint(Bs[s][(kb + 4) * BSTRIDE + n0]);
            }
#pragma unroll
            for (int mt = 0; mt < 4; mt++)
#pragma unroll
                for (int nt = 0; nt < 4; nt++)
                    mma_tf32(acc[mt][nt], afr[mt], bfr[nt]);
        }

        // store prefetched tile into the other stage
        if (t + 1 < T) {
            const int ns = s ^ 1;
            float4 ca;
            ca.x = f2tf32(pa0.x); ca.y = f2tf32(pa0.y); ca.z = f2tf32(pa0.z); ca.w = f2tf32(pa0.w);
            *reinterpret_cast<float4*>(&As[ns][rowA * ASTRIDE + kqA]) = ca;
            ca.x = f2tf32(pa1.x); ca.y = f2tf32(pa1.y); ca.z = f2tf32(pa1.z); ca.w = f2tf32(pa1.w);
            *reinterpret_cast<float4*>(&As[ns][(rowA + 64) * ASTRIDE + kqA]) = ca;
            ca.x = f2tf32(pb0.x); ca.y = f2tf32(pb0.y); ca.z = f2tf32(pb0.z); ca.w = f2tf32(pb0.w);
            *reinterpret_cast<float4*>(&Bs[ns][kB * BSTRIDE + nB]) = ca;
            ca.x = f2tf32(pb1.x); ca.y = f2tf32(pb1.y); ca.z = f2tf32(pb1.z); ca.w = f2tf32(pb1.w);
            *reinterpret_cast<float4*>(&Bs[ns][(kB + 8) * BSTRIDE + nB]) = ca;
            __syncthreads();
            s = ns;
        }
    }

    // ---- epilogue ----
#pragma unroll
    for (int mt = 0; mt < 4; mt++) {
        const int r0 = bm + warpM * 64 + mt * 16 + (lane >> 2);
        const int r1 = r0 + 8;
#pragma unroll
        for (int nt = 0; nt < 4; nt++) {
            const int c = bn + warpN * 32 + nt * 8 + ((lane & 3) << 1);
            float2 v0 = make_float2(acc[mt][nt].x, acc[mt][nt].y);
            float2 v1 = make_float2(acc[mt][nt].z, acc[mt][nt].w);
            if (BIAS) {
                float2 bb = *reinterpret_cast<const float2*>(&bias[c]);
                v0.x += bb.x; v0.y += bb.y;
                v1.x += bb.x; v1.y += bb.y;
            }
            if (RES) {
                float2 r0v = *reinterpret_cast<const float2*>(&res[(size_t)r0 * ldc + c]);
                float2 r1v = *reinterpret_cast<const float2*>(&res[(size_t)r1 * ldc + c]);
                v0.x += r0v.x; v0.y += r0v.y;
                v1.x += r1v.x; v1.y += r1v.y;
            }
            if (RELU) {
                v0.x = fmaxf(v0.x, 0.f); v0.y = fmaxf(v0.y, 0.f);
                v1.x = fmaxf(v1.x, 0.f); v1.y = fmaxf(v1.y, 0.f);
            }
            *reinterpret_cast<float2*>(&C[(size_t)r0 * ldc + c]) = v0;
            *reinterpret_cast<float2*>(&C[(size_t)r1 * ldc + c]) = v1;
        }
    }
}

// =====================================================================
// LayerNorm: one block (256 threads) per row of 768.
// =====================================================================
__global__ __launch_bounds__(256)
void ln_k(const float* __restrict__ x, const float* __restrict__ s,
          const float* __restrict__ b, float* __restrict__ h)
{
    __shared__ float red[16];
    const int row = blockIdx.x;
    const int tid = threadIdx.x;
    const float* xr = x + (size_t)row * Dq;
    float*       hr = h + (size_t)row * Dq;

    float v0 = xr[tid], v1 = xr[tid + 256], v2 = xr[tid + 512];
    float sum = v0 + v1 + v2;
    float sq  = v0 * v0 + v1 * v1 + v2 * v2;
#pragma unroll
    for (int off = 16; off; off >>= 1) {
        sum += __shfl_xor_sync(0xffffffffu, sum, off);
        sq  += __shfl_xor_sync(0xffffffffu, sq,  off);
    }
    const int warp = tid >> 5, lane = tid & 31;
    if (lane == 0) { red[warp] = sum; red[warp + 8] = sq; }
    __syncthreads();
    if (tid < 32) {
        float a = (tid < 8) ? red[tid] : 0.f;
        float c = (tid < 8) ? red[tid + 8] : 0.f;
#pragma unroll
        for (int off = 4; off; off >>= 1) {
            a += __shfl_xor_sync(0xffffffffu, a, off);
            c += __shfl_xor_sync(0xffffffffu, c, off);
        }
        if (tid == 0) { red[0] = a; red[1] = c; }
    }
    __syncthreads();
    const float mean = red[0] * (1.f / Dq);
    const float var  = red[1] * (1.f / Dq) - mean * mean;
    const float rstd = rsqrtf(var + 1e-5f);
    hr[tid]       = (v0 - mean) * rstd * s[tid]       + b[tid];
    hr[tid + 256] = (v1 - mean) * rstd * s[tid + 256] + b[tid + 256];
    hr[tid + 512] = (v2 - mean) * rstd * s[tid + 512] + b[tid + 512];
}

// =====================================================================
// Attention: one block per (batch, head). N=80, DH=96.
// =====================================================================
#define LDK 104
__global__ __launch_bounds__(256)
void attn_k(const float* __restrict__ q, const float* __restrict__ kv,
            float* __restrict__ o)
{
    extern __shared__ float sm[];
    float* qs = sm;                       // 80*96
    float* ks = qs + 80 * 96;             // 80*104
    float* vs = ks + 80 * LDK;            // 80*104
    float* sc = vs + 80 * LDK;            // 80*80

    const int bh = blockIdx.x;
    const int b  = bh >> 3;
    const int hh = bh & 7;
    const int tid = threadIdx.x;

    const float* qg  = q  + (size_t)b * Nseq * Dq      + hh * DHq;
    const float* kvg = kv + (size_t)b * Nseq * (2 * Dq) + hh * DHq;

    for (int idx = tid; idx < 80 * 96; idx += 256) {
        const int n = idx / 96, d = idx - n * 96;
        qs[n * 96 + d]  = qg [(size_t)n * Dq + d];
        ks[n * LDK + d] = kvg[(size_t)n * 2 * Dq + d];
        vs[n * LDK + d] = kvg[(size_t)n * 2 * Dq + Dq + d];
    }
    __syncthreads();

    const float scale = 0.10206207261596577f;   // 96^-0.5
    for (int idx = tid; idx < 80 * 80; idx += 256) {
        const int i = idx / 80, j = idx - i * 80;
        const float4* qr = reinterpret_cast<const float4*>(qs + i * 96);
        const float4* kr = reinterpret_cast<const float4*>(ks + j * LDK);
        float acc = 0.f;
#pragma unroll
        for (int t = 0; t < 24; t++) {
            float4 a = qr[t], c = kr[t];
            acc += a.x * c.x + a.y * c.y + a.z * c.z + a.w * c.w;
        }
        sc[idx] = acc * scale;
    }
    __syncthreads();

    const int warp = tid >> 5, lane = tid & 31;
#pragma unroll
    for (int r = 0; r < 10; r++) {
        float* row = sc + (warp * 10 + r) * 80;
        float m = -1e30f;
        for (int j = lane; j < 80; j += 32) m = fmaxf(m, row[j]);
#pragma unroll
        for (int off = 16; off; off >>= 1) m = fmaxf(m, __shfl_xor_sync(0xffffffffu, m, off));
        float ssum = 0.f;
        for (int j = lane; j < 80; j += 32) {
            float e = __expf(row[j] - m);
            row[j] = e;
            ssum += e;
        }
#pragma unroll
        for (int off = 16; off; off >>= 1) ssum += __shfl_xor_sync(0xffffffffu, ssum, off);
        const float inv = 1.f / ssum;
        for (int j = lane; j < 80; j += 32) row[j] *= inv;
    }
    __syncthreads();

    float* og = o + (size_t)b * Nseq * Dq + hh * DHq;
    for (int idx = tid; idx < 80 * 96; idx += 256) {
        const int i = idx / 96, d = idx - i * 96;
        const float* row = sc + i * 80;
        float acc = 0.f;
#pragma unroll 8
        for (int j = 0; j < 80; j++) acc = fmaf(row[j], vs[j * LDK + d], acc);
        og[(size_t)i * Dq + d] = acc;
    }
}

// ---------------- prefix broadcast & output gather ----------------
__global__ void prefix_k(const float* __restrict__ pc, float* __restrict__ x)
{
    const int idx = blockIdx.x * blockDim.x + threadIdx.x;  // B*PL*D
    if (idx >= Bq * PLq * Dq) return;
    const int d = idx % Dq;
    const int p = (idx / Dq) % PLq;
    const int b = idx / (Dq * PLq);
    x[((size_t)b * Nseq + CLq + p) * Dq + d] = pc[p * Dq + d];
}

__global__ void gather_k(const float* __restrict__ x, float* __restrict__ out)
{
    const int idx = blockIdx.x * blockDim.x + threadIdx.x;  // B*PL*D
    if (idx >= Bq * PLq * Dq) return;
    const int d = idx % Dq;
    const int p = (idx / Dq) % PLq;
    const int b = idx / (Dq * PLq);
    out[idx] = x[((size_t)b * Nseq + CLq + p) * Dq + d];
}

// =====================================================================
// host driver
// =====================================================================
extern "C" void kernel_launch(void* const* d_in, const int* in_sizes, int n_in,
                              void* d_out, int out_size)
{
    (void)in_sizes; (void)n_in; (void)out_size;
    const float* latent       = (const float*)d_in[0];
    const float* lin_w        = (const float*)d_in[1];
    const float* lin_b        = (const float*)d_in[2];
    const float* map_w        = (const float*)d_in[3];
    const float* map_b        = (const float*)d_in[4];
    const float* prefix_const = (const float*)d_in[5];
    const float* ln1_s        = (const float*)d_in[6];
    const float* ln1_b        = (const float*)d_in[7];
    const float* wq           = (const float*)d_in[8];
    const float* wkv          = (const float*)d_in[9];
    const float* wo           = (const float*)d_in[10];
    const float* bo           = (const float*)d_in[11];
    const float* ln2_s        = (const float*)d_in[12];
    const float* ln2_b        = (const float*)d_in[13];
    const float* w1           = (const float*)d_in[14];
    const float* b1           = (const float*)d_in[15];
    const float* w2           = (const float*)d_in[16];
    const float* b2           = (const float*)d_in[17];
    float* out = (float*)d_out;

    float *lat, *x, *h, *q, *kvb, *o, *mid;
    cudaGetSymbolAddress((void**)&lat, g_lat);
    cudaGetSymbolAddress((void**)&x,   g_x);
    cudaGetSymbolAddress((void**)&h,   g_h);
    cudaGetSymbolAddress((void**)&q,   g_q);
    cudaGetSymbolAddress((void**)&kvb, g_kv);
    cudaGetSymbolAddress((void**)&o,   g_o);
    cudaGetSymbolAddress((void**)&mid, g_mid);

    const int attn_smem = 30720 * (int)sizeof(float);   // 122880 B
    cudaFuncSetAttribute(attn_k, cudaFuncAttributeMaxDynamicSharedMemorySize, attn_smem);

    // 1) lat = latent @ lin_w + lin_b            (256x512) @ (512x512)
    tf32gemm_k<true, false, false><<<dim3(Pq / 128, Bq / 128), 256>>>(
        latent, lin_w, lat, lin_b, nullptr, Bq, Pq, Eq, Pq);

    // 2) seq[:, :40] = lat @ map_w + map_b       (256x512) @ (512x30720)
    tf32gemm_k<true, false, false><<<dim3((CLq * Dq) / 128, Bq / 128), 256>>>(
        lat, map_w, x, map_b, nullptr, Bq, CLq * Dq, Pq, Nseq * Dq);

    // 3) seq[:, 40:] = prefix_const (broadcast)
    prefix_k<<<(Bq * PLq * Dq + 255) / 256, 256>>>(prefix_const, x);

    // 4) transformer layers
    for (int l = 0; l < Lq; l++) {
        const float* wq_l  = wq  + (size_t)l * Dq * Dq;
        const float* wkv_l = wkv + (size_t)l * Dq * 2 * Dq;
        const float* wo_l  = wo  + (size_t)l * Dq * Dq;
        const float* bo_l  = bo  + (size_t)l * Dq;
        const float* w1_l  = w1  + (size_t)l * Dq * MHq;
        const float* b1_l  = b1  + (size_t)l * MHq;
        const float* w2_l  = w2  + (size_t)l * MHq * Dq;
        const float* b2_l  = b2  + (size_t)l * Dq;

        // h = LN1(x)
        ln_k<<<ROWS, 256>>>(x, ln1_s + (size_t)l * Dq, ln1_b + (size_t)l * Dq, h);

        // q = h @ wq ; kv = h @ wkv
        tf32gemm_k<false, false, false><<<dim3(Dq / 128, ROWS / 128), 256>>>(
            h, wq_l, q, nullptr, nullptr, ROWS, Dq, Dq, Dq);
        tf32gemm_k<false, false, false><<<dim3((2 * Dq) / 128, ROWS / 128), 256>>>(
            h, wkv_l, kvb, nullptr, nullptr, ROWS, 2 * Dq, Dq, 2 * Dq);

        // o = attention(q, k, v)
        attn_k<<<Bq * Hq, 256, attn_smem>>>(q, kvb, o);

        // x = x + o @ wo + bo
        tf32gemm_k<true, true, false><<<dim3(Dq / 128, ROWS / 128), 256>>>(
            o, wo_l, x, bo_l, x, ROWS, Dq, Dq, Dq);

        // h = LN2(x)
        ln_k<<<ROWS, 256>>>(x, ln2_s + (size_t)l * Dq, ln2_b + (size_t)l * Dq, h);

        // mid = relu(h @ w1 + b1)
        tf32gemm_k<true, false, true><<<dim3(MHq / 128, ROWS / 128), 256>>>(
            h, w1_l, mid, b1_l, nullptr, ROWS, MHq, Dq, MHq);

        // x = x + mid @ w2 + b2
        tf32gemm_k<true, true, false><<<dim3(Dq / 128, ROWS / 128), 256>>>(
            mid, w2_l, x, b2_l, x, ROWS, Dq, MHq, Dq);
    }

    // 5) out = x[:, CL:, :]
    gather_k<<<(Bq * PLq * Dq + 255) / 256, 256>>>(x, out);
}

// round 12
// speedup vs baseline: 1.0053x; 1.0053x over previous
#include <cuda_runtime.h>
#include <cuda_bf16.h>
#include <cstdint>
#include <cstdio>

// ---------------- problem constants ----------------
#define Bq   256
#define Eq   512
#define Pq   512
#define Dq   768
#define Hq   8
#define DHq  96
#define CLq  40
#define PLq  40
#define Lq   8
#define MHq  1536
#define Nseq 80                 // CL + PL
#define ROWS (Bq * Nseq)        // 20480 token rows

// ---------------- scratch (device globals, no allocation) ----------------
__device__ float g_lat[Bq * Pq];                    // 256x512
__device__ float g_x  [(size_t)ROWS * Dq];          // residual stream
__device__ float g_h  [(size_t)ROWS * Dq];          // LN output
__device__ float g_q  [(size_t)ROWS * Dq];
__device__ float g_kv [(size_t)ROWS * 2 * Dq];
__device__ float g_o  [(size_t)ROWS * Dq];
__device__ float g_mid[(size_t)ROWS * MHq];

// =====================================================================
// TF32 tensor-core GEMM: C[M,N] = A[M,K] @ B[K,N] (+bias, +res, +relu)
// row-major. Requires M%128==0, N%128==0, K%16==0 (all shapes comply).
// Block tile 128x128x16, 256 threads = 8 warps (2x4), warp tile 64x32,
// per warp 4x4 mma.sync.m16n8k8.tf32 per 8-wide k-step.
// Double-buffered smem. A in smem as [m][20] (pad), B as [k][136] (pad):
// both give conflict-free fragment LDS.
// =====================================================================
#define ASTRIDE 20
#define BSTRIDE 136

__device__ __forceinline__ float f2tf32(float x) {
    uint32_t u;
    asm("cvt.rna.tf32.f32 %0, %1;" : "=r"(u) : "f"(x));
    return __uint_as_float(u);
}

__device__ __forceinline__ void mma_tf32(float4& d, const uint32_t a[4], const uint32_t b[2]) {
    asm volatile(
        "mma.sync.aligned.m16n8k8.row.col.f32.tf32.tf32.f32 "
        "{%0,%1,%2,%3}, {%4,%5,%6,%7}, {%8,%9}, {%0,%1,%2,%3};"
        : "+f"(d.x), "+f"(d.y), "+f"(d.z), "+f"(d.w)
        : "r"(a[0]), "r"(a[1]), "r"(a[2]), "r"(a[3]),
          "r"(b[0]), "r"(b[1]));
}

template <bool BIAS, bool RES, bool RELU>
__global__ __launch_bounds__(256)
void tf32gemm_k(const float* __restrict__ A, const float* __restrict__ B,
                float* __restrict__ C, const float* __restrict__ bias,
                const float* __restrict__ res,
                int M, int N, int K, int ldc)
{
    __shared__ float As[2][128 * ASTRIDE];   // [m][k] (k in 0..15, pad to 20)
    __shared__ float Bs[2][16 * BSTRIDE];    // [k][n] (n in 0..127, pad to 136)

    const int tid  = threadIdx.x;
    const int lane = tid & 31;
    const int warp = tid >> 5;
    const int warpM = warp >> 2;       // 0..1
    const int warpN = warp & 3;        // 0..3
    const int bm = blockIdx.y * 128;
    const int bn = blockIdx.x * 128;

    // global load mapping
    // A tile: 128 rows x 16 cols = 512 float4 chunks; thread t -> chunk t and t+256
    const int rowA = tid >> 2;                 // 0..63  (second chunk = +64)
    const int kqA  = (tid & 3) * 4;            // 0,4,8,12
    // B tile: 16 rows x 128 cols = 512 float4 chunks
    const int kB   = tid >> 5;                 // 0..7   (second chunk = +8)
    const int nB   = (tid & 31) * 4;           // 0..124

    const float* aG = A + (size_t)(bm + rowA) * K + kqA;
    const float* bG = B + (size_t)kB * N + bn + nB;
    const size_t aG2 = (size_t)64 * K;         // offset to second A chunk
    const size_t bG2 = (size_t)8 * N;          // offset to second B chunk

    float4 acc[4][4];
#pragma unroll
    for (int i = 0; i < 4; i++)
#pragma unroll
        for (int j = 0; j < 4; j++) acc[i][j] = make_float4(0.f, 0.f, 0.f, 0.f);

    // ---- preload tile 0 ----
    float4 pa0 = *reinterpret_cast<const float4*>(aG);
    float4 pa1 = *reinterpret_cast<const float4*>(aG + aG2);
    float4 pb0 = *reinterpret_cast<const float4*>(bG);
    float4 pb1 = *reinterpret_cast<const float4*>(bG + bG2);

    int s = 0;
    {
        float4 ca;
        ca.x = f2tf32(pa0.x); ca.y = f2tf32(pa0.y); ca.z = f2tf32(pa0.z); ca.w = f2tf32(pa0.w);
        *reinterpret_cast<float4*>(&As[0][rowA * ASTRIDE + kqA]) = ca;
        ca.x = f2tf32(pa1.x); ca.y = f2tf32(pa1.y); ca.z = f2tf32(pa1.z); ca.w = f2tf32(pa1.w);
        *reinterpret_cast<float4*>(&As[0][(rowA + 64) * ASTRIDE + kqA]) = ca;
        ca.x = f2tf32(pb0.x); ca.y = f2tf32(pb0.y); ca.z = f2tf32(pb0.z); ca.w = f2tf32(pb0.w);
        *reinterpret_cast<float4*>(&Bs[0][kB * BSTRIDE + nB]) = ca;
        ca.x = f2tf32(pb1.x); ca.y = f2tf32(pb1.y); ca.z = f2tf32(pb1.z); ca.w = f2tf32(pb1.w);
        *reinterpret_cast<float4*>(&Bs[0][(kB + 8) * BSTRIDE + nB]) = ca;
    }
    __syncthreads();

    const int T = K / 16;
    for (int t = 0; t < T; t++) {
        // prefetch next tile into registers
        if (t + 1 < T) {
            const int k0 = (t + 1) * 16;
            pa0 = *reinterpret_cast<const float4*>(aG + k0);
            pa1 = *reinterpret_cast<const float4*>(aG + k0 + aG2);
            pb0 = *reinterpret_cast<const float4*>(bG + (size_t)k0 * N);
            pb1 = *reinterpret_cast<const float4*>(bG + (size_t)k0 * N + bG2);
        }

        // compute two 8-wide k-steps from stage s
#pragma unroll
        for (int kk = 0; kk < 16; kk += 8) {
            const int kb = kk + (lane & 3);
            uint32_t afr[4][4];
            uint32_t bfr[4][2];
#pragma unroll
            for (int mt = 0; mt < 4; mt++) {
                const int m0 = warpM * 64 + mt * 16 + (lane >> 2);
                afr[mt][0] = __float_as_uint(As[s][m0 * ASTRIDE + kb]);
                afr[mt][1] = __float_as_uint(As[s][(m0 + 8) * ASTRIDE + kb]);
                afr[mt][2] = __float_as_uint(As[s][m0 * ASTRIDE + kb + 4]);
                afr[mt][3] = __float_as_uint(As[s][(m0 + 8) * ASTRIDE + kb + 4]);
            }
#pragma unroll
            for (int nt = 0; nt < 4; nt++) {
                const int n0 = warpN * 32 + nt * 8 + (lane >> 2);
                bfr[nt][0] = __float_as_uint(Bs[s][kb * BSTRIDE + n0]);
                bfr[nt][1] = __float_as_uint(Bs[s][(kb + 4) * BSTRIDE + n0]);
            }
#pragma unroll
            for (int mt = 0; mt < 4; mt++)
#pragma unroll
                for (int nt = 0; nt < 4; nt++)
                    mma_tf32(acc[mt][nt], afr[mt], bfr[nt]);
        }

        // store prefetched tile into the other stage
        if (t + 1 < T) {
            const int ns = s ^ 1;
            float4 ca;
            ca.x = f2tf32(pa0.x); ca.y = f2tf32(pa0.y); ca.z = f2tf32(pa0.z); ca.w = f2tf32(pa0.w);
            *reinterpret_cast<float4*>(&As[ns][rowA * ASTRIDE + kqA]) = ca;
            ca.x = f2tf32(pa1.x); ca.y = f2tf32(pa1.y); ca.z = f2tf32(pa1.z); ca.w = f2tf32(pa1.w);
            *reinterpret_cast<float4*>(&As[ns][(rowA + 64) * ASTRIDE + kqA]) = ca;
            ca.x = f2tf32(pb0.x); ca.y = f2tf32(pb0.y); ca.z = f2tf32(pb0.z); ca.w = f2tf32(pb0.w);
            *reinterpret_cast<float4*>(&Bs[ns][kB * BSTRIDE + nB]) = ca;
            ca.x = f2tf32(pb1.x); ca.y = f2tf32(pb1.y); ca.z = f2tf32(pb1.z); ca.w = f2tf32(pb1.w);
            *reinterpret_cast<float4*>(&Bs[ns][(kB + 8) * BSTRIDE + nB]) = ca;
            __syncthreads();
            s = ns;
        }
    }

    // ---- epilogue ----
#pragma unroll
    for (int mt = 0; mt < 4; mt++) {
        const int r0 = bm + warpM * 64 + mt * 16 + (lane >> 2);
        const int r1 = r0 + 8;
#pragma unroll
        for (int nt = 0; nt < 4; nt++) {
            const int c = bn + warpN * 32 + nt * 8 + ((lane & 3) << 1);
            float2 v0 = make_float2(acc[mt][nt].x, acc[mt][nt].y);
            float2 v1 = make_float2(acc[mt][nt].z, acc[mt][nt].w);
            if (BIAS) {
                float2 bb = *reinterpret_cast<const float2*>(&bias[c]);
                v0.x += bb.x; v0.y += bb.y;
                v1.x += bb.x; v1.y += bb.y;
            }
            if (RES) {
                float2 r0v = *reinterpret_cast<const float2*>(&res[(size_t)r0 * ldc + c]);
                float2 r1v = *reinterpret_cast<const float2*>(&res[(size_t)r1 * ldc + c]);
                v0.x += r0v.x; v0.y += r0v.y;
                v1.x += r1v.x; v1.y += r1v.y;
            }
            if (RELU) {
                v0.x = fmaxf(v0.x, 0.f); v0.y = fmaxf(v0.y, 0.f);
                v1.x = fmaxf(v1.x, 0.f); v1.y = fmaxf(v1.y, 0.f);
            }
            *reinterpret_cast<float2*>(&C[(size_t)r0 * ldc + c]) = v0;
            *reinterpret_cast<float2*>(&C[(size_t)r1 * ldc + c]) = v1;
        }
    }
}

// =====================================================================
// LayerNorm: one block (256 threads) per row of 768.
// =====================================================================
__global__ __launch_bounds__(256)
void ln_k(const float* __restrict__ x, const float* __restrict__ s,
          const float* __restrict__ b, float* __restrict__ h)
{
    __shared__ float red[16];
    const int row = blockIdx.x;
    const int tid = threadIdx.x;
    const float* xr = x + (size_t)row * Dq;
    float*       hr = h + (size_t)row * Dq;

    float v0 = xr[tid], v1 = xr[tid + 256], v2 = xr[tid + 512];
    float sum = v0 + v1 + v2;
    float sq  = v0 * v0 + v1 * v1 + v2 * v2;
#pragma unroll
    for (int off = 16; off; off >>= 1) {
        sum += __shfl_xor_sync(0xffffffffu, sum, off);
        sq  += __shfl_xor_sync(0xffffffffu, sq,  off);
    }
    const int warp = tid >> 5, lane = tid & 31;
    if (lane == 0) { red[warp] = sum; red[warp + 8] = sq; }
    __syncthreads();
    if (tid < 32) {
        float a = (tid < 8) ? red[tid] : 0.f;
        float c = (tid < 8) ? red[tid + 8] : 0.f;
#pragma unroll
        for (int off = 4; off; off >>= 1) {
            a += __shfl_xor_sync(0xffffffffu, a, off);
            c += __shfl_xor_sync(0xffffffffu, c, off);
        }
        if (tid == 0) { red[0] = a; red[1] = c; }
    }
    __syncthreads();
    const float mean = red[0] * (1.f / Dq);
    const float var  = red[1] * (1.f / Dq) - mean * mean;
    const float rstd = rsqrtf(var + 1e-5f);
    hr[tid]       = (v0 - mean) * rstd * s[tid]       + b[tid];
    hr[tid + 256] = (v1 - mean) * rstd * s[tid + 256] + b[tid + 256];
    hr[tid + 512] = (v2 - mean) * rstd * s[tid + 512] + b[tid + 512];
}

// =====================================================================
// Attention: one block per (batch, head). N=80, DH=96.
// =====================================================================
#define LDK 104
__global__ __launch_bounds__(256)
void attn_k(const float* __restrict__ q, const float* __restrict__ kv,
            float* __restrict__ o)
{
    extern __shared__ float sm[];
    float* qs = sm;                       // 80*96
    float* ks = qs + 80 * 96;             // 80*104
    float* vs = ks + 80 * LDK;            // 80*104
    float* sc = vs + 80 * LDK;            // 80*80

    const int bh = blockIdx.x;
    const int b  = bh >> 3;
    const int hh = bh & 7;
    const int tid = threadIdx.x;

    const float* qg  = q  + (size_t)b * Nseq * Dq      + hh * DHq;
    const float* kvg = kv + (size_t)b * Nseq * (2 * Dq) + hh * DHq;

    for (int idx = tid; idx < 80 * 96; idx += 256) {
        const int n = idx / 96, d = idx - n * 96;
        qs[n * 96 + d]  = qg [(size_t)n * Dq + d];
        ks[n * LDK + d] = kvg[(size_t)n * 2 * Dq + d];
        vs[n * LDK + d] = kvg[(size_t)n * 2 * Dq + Dq + d];
    }
    __syncthreads();

    const float scale = 0.10206207261596577f;   // 96^-0.5
    for (int idx = tid; idx < 80 * 80; idx += 256) {
        const int i = idx / 80, j = idx - i * 80;
        const float4* qr = reinterpret_cast<const float4*>(qs + i * 96);
        const float4* kr = reinterpret_cast<const float4*>(ks + j * LDK);
        float acc = 0.f;
#pragma unroll
        for (int t = 0; t < 24; t++) {
            float4 a = qr[t], c = kr[t];
            acc += a.x * c.x + a.y * c.y + a.z * c.z + a.w * c.w;
        }
        sc[idx] = acc * scale;
    }
    __syncthreads();

    const int warp = tid >> 5, lane = tid & 31;
#pragma unroll
    for (int r = 0; r < 10; r++) {
        float* row = sc + (warp * 10 + r) * 80;
        float m = -1e30f;
        for (int j = lane; j < 80; j += 32) m = fmaxf(m, row[j]);
#pragma unroll
        for (int off = 16; off; off >>= 1) m = fmaxf(m, __shfl_xor_sync(0xffffffffu, m, off));
        float ssum = 0.f;
        for (int j = lane; j < 80; j += 32) {
            float e = __expf(row[j] - m);
            row[j] = e;
            ssum += e;
        }
#pragma unroll
        for (int off = 16; off; off >>= 1) ssum += __shfl_xor_sync(0xffffffffu, ssum, off);
        const float inv = 1.f / ssum;
        for (int j = lane; j < 80; j += 32) row[j] *= inv;
    }
    __syncthreads();

    float* og = o + (size_t)b * Nseq * Dq + hh * DHq;
    for (int idx = tid; idx < 80 * 96; idx += 256) {
        const int i = idx / 96, d = idx - i * 96;
        const float* row = sc + i * 80;
        float acc = 0.f;
#pragma unroll 8
        for (int j = 0; j < 80; j++) acc = fmaf(row[j], vs[j * LDK + d], acc);
        og[(size_t)i * Dq + d] = acc;
    }
}

// ---------------- prefix broadcast & output gather ----------------
__global__ void prefix_k(const float* __restrict__ pc, float* __restrict__ x)
{
    const int idx = blockIdx.x * blockDim.x + threadIdx.x;  // B*PL*D
    if (idx >= Bq * PLq * Dq) return;
    const int d = idx % Dq;
    const int p = (idx / Dq) % PLq;
    const int b = idx / (Dq * PLq);
    x[((size_t)b * Nseq + CLq + p) * Dq + d] = pc[p * Dq + d];
}

__global__ void gather_k(const float* __restrict__ x, float* __restrict__ out)
{
    const int idx = blockIdx.x * blockDim.x + threadIdx.x;  // B*PL*D
    if (idx >= Bq * PLq * Dq) return;
    const int d = idx % Dq;
    const int p = (idx / Dq) % PLq;
    const int b = idx / (Dq * PLq);
    out[idx] = x[((size_t)b * Nseq + CLq + p) * Dq + d];
}

// =====================================================================
// host driver
// =====================================================================
extern "C" void kernel_launch(void* const* d_in, const int* in_sizes, int n_in,
                              void* d_out, int out_size)
{
    (void)in_sizes; (void)n_in; (void)out_size;
    const float* latent       = (const float*)d_in[0];
    const float* lin_w        = (const float*)d_in[1];
    const float* lin_b        = (const float*)d_in[2];
    const float* map_w        = (const float*)d_in[3];
    const float* map_b        = (const float*)d_in[4];
    const float* prefix_const = (const float*)d_in[5];
    const float* ln1_s        = (const float*)d_in[6];
    const float* ln1_b        = (const float*)d_in[7];
    const float* wq           = (const float*)d_in[8];
    const float* wkv          = (const float*)d_in[9];
    const float* wo           = (const float*)d_in[10];
    const float* bo           = (const float*)d_in[11];
    const float* ln2_s        = (const float*)d_in[12];
    const float* ln2_b        = (const float*)d_in[13];
    const float* w1           = (const float*)d_in[14];
    const float* b1           = (const float*)d_in[15];
    const float* w2           = (const float*)d_in[16];
    const float* b2           = (const float*)d_in[17];
    float* out = (float*)d_out;

    float *lat, *x, *h, *q, *kvb, *o, *mid;
    cudaGetSymbolAddress((void**)&lat, g_lat);
    cudaGetSymbolAddress((void**)&x,   g_x);
    cudaGetSymbolAddress((void**)&h,   g_h);
    cudaGetSymbolAddress((void**)&q,   g_q);
    cudaGetSymbolAddress((void**)&kvb, g_kv);
    cudaGetSymbolAddress((void**)&o,   g_o);
    cudaGetSymbolAddress((void**)&mid, g_mid);

    const int attn_smem = 30720 * (int)sizeof(float);   // 122880 B
    cudaFuncSetAttribute(attn_k, cudaFuncAttributeMaxDynamicSharedMemorySize, attn_smem);

    // 1) lat = latent @ lin_w + lin_b            (256x512) @ (512x512)
    tf32gemm_k<true, false, false><<<dim3(Pq / 128, Bq / 128), 256>>>(
        latent, lin_w, lat, lin_b, nullptr, Bq, Pq, Eq, Pq);

    // 2) seq[:, :40] = lat @ map_w + map_b       (256x512) @ (512x30720)
    tf32gemm_k<true, false, false><<<dim3((CLq * Dq) / 128, Bq / 128), 256>>>(
        lat, map_w, x, map_b, nullptr, Bq, CLq * Dq, Pq, Nseq * Dq);

    // 3) seq[:, 40:] = prefix_const (broadcast)
    prefix_k<<<(Bq * PLq * Dq + 255) / 256, 256>>>(prefix_const, x);

    // 4) transformer layers
    for (int l = 0; l < Lq; l++) {
        const float* wq_l  = wq  + (size_t)l * Dq * Dq;
        const float* wkv_l = wkv + (size_t)l * Dq * 2 * Dq;
        const float* wo_l  = wo  + (size_t)l * Dq * Dq;
        const float* bo_l  = bo  + (size_t)l * Dq;
        const float* w1_l  = w1  + (size_t)l * Dq * MHq;
        const float* b1_l  = b1  + (size_t)l * MHq;
        const float* w2_l  = w2  + (size_t)l * MHq * Dq;
        const float* b2_l  = b2  + (size_t)l * Dq;

        // h = LN1(x)
        ln_k<<<ROWS, 256>>>(x, ln1_s + (size_t)l * Dq, ln1_b + (size_t)l * Dq, h);

        // q = h @ wq ; kv = h @ wkv
        tf32gemm_k<false, false, false><<<dim3(Dq / 128, ROWS / 128), 256>>>(
            h, wq_l, q, nullptr, nullptr, ROWS, Dq, Dq, Dq);
        tf32gemm_k<false, false, false><<<dim3((2 * Dq) / 128, ROWS / 128), 256>>>(
            h, wkv_l, kvb, nullptr, nullptr, ROWS, 2 * Dq, Dq, 2 * Dq);

        // o = attention(q, k, v)
        attn_k<<<Bq * Hq, 256, attn_smem>>>(q, kvb, o);

        // x = x + o @ wo + bo
        tf32gemm_k<true, true, false><<<dim3(Dq / 128, ROWS / 128), 256>>>(
            o, wo_l, x, bo_l, x, ROWS, Dq, Dq, Dq);

        // h = LN2(x)
        ln_k<<<ROWS, 256>>>(x, ln2_s + (size_t)l * Dq, ln2_b + (size_t)l * Dq, h);

        // mid = relu(h @ w1 + b1)
        tf32gemm_k<true, false, true><<<dim3(MHq / 128, ROWS / 128), 256>>>(
            h, w1_l, mid, b1_l, nullptr, ROWS, MHq, Dq, MHq);

        // x = x + mid @ w2 + b2
        tf32gemm_k<true, true, false><<<dim3(Dq / 128, ROWS / 128), 256>>>(
            mid, w2_l, x, b2_l, x, ROWS, Dq, MHq, Dq);
    }

    // 5) out = x[:, CL:, :]
    gather_k<<<(Bq * PLq * Dq + 255) / 256, 256>>>(x, out);
}